// round 14
// baseline (speedup 1.0000x reference)
#include <cuda_runtime.h>

#define NB 32
#define NPTS 512
#define NC 64
#define PIX (NC * NC)          // 4096
#define ROWS (NPTS + 1)        // 513
#define INV2S2 0.0078125f      // 1/(2*8^2)
#define BG_RATIO 0.15f

// ---------------------------------------------------------------------------
// Single fused kernel. CTA = (batch b, chain c) owns i rows [16c, 16c+16),
// processed as a chain of 4 tiles x 4 rows. 256 threads:
//   p  = t & 1        n-parity (thread reduces/stores n == p mod 2)
//   jp = (t>>1) & 31  j pair (j = 2jp, 2jp+1)
//   i2 = t >> 6       row within tile
// Partial S/M over a parity combine with one __shfl_xor (lanes t, t^1 pair).
//
// Build: thread t computes rows n = t, t+256 of
//   sEx[n][j] = exp(-(x^2-2xc_j+c_j^2)/128)   (64 cols)
//   sEyT[h][n] (h = 0..15, cols i0..i0+15, transposed)
// directly from points[b] + cood.
//
// A (exposed, DRAM idle -> minimized: only 4 rows): reduce tile0 -> inv.
// Loop k=0..3: store tile k (streaming __stcs) while reducing tile k+1.
// Softmax identity: out = Ey*Ex/(S+ebg); bg = ebg/(S+ebg);
// min_dis = max(0, -128 ln(max_n Ey*Ex)). Exact quotient, no max-shift.
// ---------------------------------------------------------------------------
#define SMEM_BYTES ((NPTS * NC + NPTS * 16 + NC) * 4)   // 164096

__device__ __forceinline__ void finalize_inv(float S0, float S1, float M0,
                                             float M1, float d,
                                             float& invx, float& invy,
                                             float& bgx, float& bgy) {
    // combine parity partners (lane pair t, t^1)
    S0 += __shfl_xor_sync(0xFFFFFFFFu, S0, 1);
    S1 += __shfl_xor_sync(0xFFFFFFFFu, S1, 1);
    M0 = fmaxf(M0, __shfl_xor_sync(0xFFFFFFFFu, M0, 1));
    M1 = fmaxf(M1, __shfl_xor_sync(0xFFFFFFFFu, M1, 1));

    float m0  = fmaxf(M0, 1e-35f);
    float m1  = fmaxf(M1, 1e-35f);
    float mn0 = fmaxf(-128.0f * __logf(m0), 0.0f);  // 2*sigma^2 = 128
    float mn1 = fmaxf(-128.0f * __logf(m1), 0.0f);
    float bd0 = d - sqrtf(mn0);
    float bd1 = d - sqrtf(mn1);
    float eb0 = __expf(-(bd0 * bd0) * INV2S2);
    float eb1 = __expf(-(bd1 * bd1) * INV2S2);
    invx = 1.0f / (S0 + eb0);
    invy = 1.0f / (S1 + eb1);
    bgx  = eb0 * invx;
    bgy  = eb1 * invy;
}

__global__ __launch_bounds__(256, 1)
void post_prob_kernel(const float* __restrict__ points,
                      const float* __restrict__ st_sizes,
                      const float* __restrict__ cood,
                      float* __restrict__ out) {
    extern __shared__ float smem[];
    float* sEx   = smem;                   // [512][64]
    float* sEyT  = smem + NPTS * NC;       // [16][512] (transposed)
    float* sCood = sEyT + 16 * NPTS;       // [64]

    int b  = blockIdx.x >> 2;
    int c  = blockIdx.x & 3;
    int i0 = c << 4;
    int t  = threadIdx.x;
    int p  = t & 1;
    int jp = (t >> 1) & 31;
    int i2 = t >> 6;                       // 0..3

    if (t < NC) sCood[t] = cood[t];
    __syncthreads();

    // ---- build phase ----
#pragma unroll
    for (int r = 0; r < 2; r++) {
        int n = t + (r << 8);
        float2 pt = *(const float2*)(points + ((size_t)b * NPTS + n) * 2);
        float x = pt.x, y = pt.y;
        float x2 = x * x, y2 = y * y;
        float tx = 2.0f * x, ty = 2.0f * y;

#pragma unroll
        for (int q = 0; q < 16; q++) {
            int jb = ((q + t) & 15) << 2;
            float4 cv = *(const float4*)&sCood[jb];
            float4 e;
            e.x = __expf(-(x2 - tx * cv.x + cv.x * cv.x) * INV2S2);
            e.y = __expf(-(x2 - tx * cv.y + cv.y * cv.y) * INV2S2);
            e.z = __expf(-(x2 - tx * cv.z + cv.z * cv.z) * INV2S2);
            e.w = __expf(-(x2 - tx * cv.w + cv.w * cv.w) * INV2S2);
            *(float4*)&sEx[n * NC + jb] = e;
        }
#pragma unroll
        for (int h = 0; h < 16; h++) {
            float cv = sCood[i0 + h];
            sEyT[h * NPTS + n] = __expf(-(y2 - ty * cv + cv * cv) * INV2S2);
        }
    }
    __syncthreads();

    const float2* exv = (const float2*)sEx + jp;   // row stride 32 float2
    float d = st_sizes[b] * BG_RATIO;
    float* outb = out + (size_t)b * ROWS * PIX;
    float* bgrow = outb + (size_t)NPTS * PIX;

    // ---- Phase A: reduce tile 0 (4 rows only; parity-split) ----
    float invx, invy;
    {
        const float* eyr = sEyT + i2 * NPTS;
        float S0 = 0.f, S1 = 0.f, M0 = 0.f, M1 = 0.f;
#pragma unroll 4
        for (int n = p; n < NPTS; n += 2) {
            float  ey = eyr[n];
            float2 ex = exv[n * 32];
            float q0 = ey * ex.x, q1 = ey * ex.y;
            S0 += q0; S1 += q1;
            M0 = fmaxf(M0, q0); M1 = fmaxf(M1, q1);
        }
        float bgx, bgy;
        finalize_inv(S0, S1, M0, M1, d, invx, invy, bgx, bgy);
        if (!p)
            __stcs((float2*)(bgrow + (i0 + i2) * NC + jp * 2),
                   make_float2(bgx, bgy));
    }

    // ---- chained store/reduce over 4 tiles ----
#pragma unroll
    for (int k = 0; k < 4; k++) {
        const float* eyc = sEyT + (4 * k + i2) * NPTS;
        float* orow = outb + (4 * k + i0 + i2) * NC + jp * 2;

        if (k < 3) {
            const float* eyn = sEyT + (4 * k + 4 + i2) * NPTS;
            float T0 = 0.f, T1 = 0.f, N0 = 0.f, N1 = 0.f;
#pragma unroll 4
            for (int n = p; n < NPTS; n += 2) {
                float2 ex = exv[n * 32];
                float  ec = eyc[n];
                float2 o;
                o.x = ec * ex.x * invx;
                o.y = ec * ex.y * invy;
                __stcs((float2*)(orow + (size_t)n * PIX), o);

                float en = eyn[n];
                float q0 = en * ex.x, q1 = en * ex.y;
                T0 += q0; T1 += q1;
                N0 = fmaxf(N0, q0); N1 = fmaxf(N1, q1);
            }
            float bgx, bgy;
            finalize_inv(T0, T1, N0, N1, d, invx, invy, bgx, bgy);
            if (!p)
                __stcs((float2*)(bgrow + (4 * k + 4 + i0 + i2) * NC + jp * 2),
                       make_float2(bgx, bgy));
        } else {
#pragma unroll 4
            for (int n = p; n < NPTS; n += 2) {
                float2 ex = exv[n * 32];
                float  ec = eyc[n];
                float2 o;
                o.x = ec * ex.x * invx;
                o.y = ec * ex.y * invy;
                __stcs((float2*)(orow + (size_t)n * PIX), o);
            }
        }
    }
}

// ---------------------------------------------------------------------------
extern "C" void kernel_launch(void* const* d_in, const int* in_sizes, int n_in,
                              void* d_out, int out_size) {
    const float* points   = (const float*)d_in[0];
    const float* st_sizes = (const float*)d_in[1];
    const float* cood     = (const float*)d_in[2];
    float*       out      = (float*)d_out;

    cudaFuncSetAttribute(post_prob_kernel,
                         cudaFuncAttributeMaxDynamicSharedMemorySize,
                         SMEM_BYTES);

    post_prob_kernel<<<NB * 4, 256, SMEM_BYTES>>>(points, st_sizes, cood, out);
}

// round 15
// speedup vs baseline: 1.0931x; 1.0931x over previous
#include <cuda_runtime.h>

#define NB 32
#define NPTS 512
#define NC 64
#define PIX (NC * NC)          // 4096
#define ROWS (NPTS + 1)        // 513
#define INV2S2 0.0078125f      // 1/(2*8^2)
#define BG_RATIO 0.15f
#define K2 (-0.011271055f)     // -INV2S2 * log2(e)

// ---------------------------------------------------------------------------
// Single fused kernel. CTA = (batch b, chain c) owns i rows [16c,16c+16),
// processed as a chain of 4 tiles x 4 rows.
// Warp w: nh = w>>2 (n-half: 256 n each), rw = w&3 (row within tile).
// Lane jp owns j = {2jp, 2jp+1}. All lanes of a warp share one n per LDS
// (conflict-free ex loads, fixing the R13 bank-conflict regression).
//
// Build (3-instr exps): sEx[n][j] = 2^(K2*(x^2-2xc_j+c_j^2)), transposed
// sEyT[h][n] likewise in y, via FFMA + FADD + ex2.approx with a K2*c^2 table.
//
// A (exposed): reduce tile0 only (4 rows, warp-pair n-split), partials to an
// 8KB double-buffered scratch, one sync, combine+finalize -> inv, bg row.
// Loop k=0..3: store tile k (each warp: its row, its 256-n half) while
// reducing tile k+1; combine at tile boundary (sync is cheap).
// Softmax identity: out = Ey*Ex/(S+ebg); bg = ebg/(S+ebg);
// min_dis = max(0, -128 ln(max_n Ey*Ex)). Exact quotient, no max-shift.
// ---------------------------------------------------------------------------
#define SP_F4 (2 * 2 * 4 * 32)                 // [buf][nh][rw][jp] float4
#define SMEM_BYTES ((NPTS*NC + 16*NPTS + 64 + 64) * 4 + SP_F4 * 16)  // 172544

__device__ __forceinline__ float ex2a(float a) {
    float r; asm("ex2.approx.f32 %0, %1;" : "=f"(r) : "f"(a)); return r;
}

__device__ __forceinline__ void finalize_sm(float S0, float S1, float M0,
                                            float M1, float d,
                                            float& invx, float& invy,
                                            float& bgx, float& bgy) {
    float m0  = fmaxf(M0, 1e-35f);
    float m1  = fmaxf(M1, 1e-35f);
    float mn0 = fmaxf(-128.0f * __logf(m0), 0.0f);  // 2*sigma^2 = 128
    float mn1 = fmaxf(-128.0f * __logf(m1), 0.0f);
    float bd0 = d - sqrtf(mn0);
    float bd1 = d - sqrtf(mn1);
    float eb0 = __expf(-(bd0 * bd0) * INV2S2);
    float eb1 = __expf(-(bd1 * bd1) * INV2S2);
    invx = 1.0f / (S0 + eb0);
    invy = 1.0f / (S1 + eb1);
    bgx  = eb0 * invx;
    bgy  = eb1 * invy;
}

__global__ __launch_bounds__(256, 1)
void post_prob_kernel(const float* __restrict__ points,
                      const float* __restrict__ st_sizes,
                      const float* __restrict__ cood,
                      float* __restrict__ out) {
    extern __shared__ float smem[];
    float*  sEx   = smem;                    // [512][64]
    float*  sEyT  = smem + NPTS * NC;        // [16][512] transposed
    float*  sCood = sEyT + 16 * NPTS;        // [64]
    float*  sC2   = sCood + 64;              // [64] = K2*c^2
    float4* sP4   = (float4*)(sC2 + 64);     // [2][2][4][32]

    int b  = blockIdx.x >> 2;
    int c  = blockIdx.x & 3;
    int i0 = c << 4;
    int t  = threadIdx.x;
    int w  = t >> 5;
    int nh = w >> 2;                         // n-half
    int rw = w & 3;                          // row within tile
    int jp = t & 31;
    int n0 = nh << 8;                        // 0 or 256

    if (t < NC) {
        float cv = cood[t];
        sCood[t] = cv;
        sC2[t]   = K2 * cv * cv;
    }
    __syncthreads();

    // ---- build phase: 3-instr exps ----
#pragma unroll
    for (int r = 0; r < 2; r++) {
        int n = t + (r << 8);
        float2 pt = *(const float2*)(points + ((size_t)b * NPTS + n) * 2);
        float Ax = K2 * pt.x * pt.x, mx = -2.0f * K2 * pt.x;
        float Ay = K2 * pt.y * pt.y, my = -2.0f * K2 * pt.y;

#pragma unroll
        for (int q = 0; q < 16; q++) {
            int jb = ((q + t) & 15) << 2;    // rotated: conflict-free STS
            float4 cv = *(const float4*)&sCood[jb];
            float4 k2 = *(const float4*)&sC2[jb];
            float4 e;
            e.x = ex2a(fmaf(mx, cv.x, Ax) + k2.x);
            e.y = ex2a(fmaf(mx, cv.y, Ax) + k2.y);
            e.z = ex2a(fmaf(mx, cv.z, Ax) + k2.z);
            e.w = ex2a(fmaf(mx, cv.w, Ax) + k2.w);
            *(float4*)&sEx[n * NC + jb] = e;
        }
#pragma unroll
        for (int h = 0; h < 16; h++) {
            sEyT[h * NPTS + n] =
                ex2a(fmaf(my, sCood[i0 + h], Ay) + sC2[i0 + h]);
        }
    }
    __syncthreads();

    const float2* exv = (const float2*)sEx + jp;   // row stride 32 float2
    float d = st_sizes[b] * BG_RATIO;
    float* outb  = out + (size_t)b * ROWS * PIX;
    float* bgrow = outb + (size_t)NPTS * PIX;

    // ---- Phase A: reduce tile0 (4 rows, warp-pair n-split) ----
    {
        const float* eyr = sEyT + rw * NPTS;
        float S0 = 0.f, S1 = 0.f, M0 = 0.f, M1 = 0.f;
#pragma unroll 2
        for (int n4 = n0; n4 < n0 + 256; n4 += 4) {
            float4 ey = *(const float4*)(eyr + n4);
            float2 e0 = exv[(n4 + 0) * 32];
            float2 e1 = exv[(n4 + 1) * 32];
            float2 e2 = exv[(n4 + 2) * 32];
            float2 e3 = exv[(n4 + 3) * 32];
            float p00 = ey.x * e0.x, p01 = ey.x * e0.y;
            float p10 = ey.y * e1.x, p11 = ey.y * e1.y;
            float p20 = ey.z * e2.x, p21 = ey.z * e2.y;
            float p30 = ey.w * e3.x, p31 = ey.w * e3.y;
            S0 += p00; S1 += p01; S0 += p10; S1 += p11;
            S0 += p20; S1 += p21; S0 += p30; S1 += p31;
            M0 = fmaxf(M0, p00); M1 = fmaxf(M1, p01);
            M0 = fmaxf(M0, p10); M1 = fmaxf(M1, p11);
            M0 = fmaxf(M0, p20); M1 = fmaxf(M1, p21);
            M0 = fmaxf(M0, p30); M1 = fmaxf(M1, p31);
        }
        sP4[((0 * 2 + nh) * 4 + rw) * 32 + jp] = make_float4(S0, S1, M0, M1);
    }
    __syncthreads();

    float invx, invy;
    {
        float4 a = sP4[((0 * 2 + 0) * 4 + rw) * 32 + jp];
        float4 q = sP4[((0 * 2 + 1) * 4 + rw) * 32 + jp];
        float bgx, bgy;
        finalize_sm(a.x + q.x, a.y + q.y, fmaxf(a.z, q.z), fmaxf(a.w, q.w),
                    d, invx, invy, bgx, bgy);
        if (nh == 0)
            *(float2*)(bgrow + (i0 + rw) * NC + jp * 2) =
                make_float2(bgx, bgy);
    }

    // ---- chained store/reduce over 4 tiles ----
#pragma unroll
    for (int k = 0; k < 4; k++) {
        const float* eyc = sEyT + (4 * k + rw) * NPTS;
        float* orow = outb + (size_t)(4 * k + i0 + rw) * NC + jp * 2;

        if (k < 3) {
            const float* eyn = eyc + 4 * NPTS;
            float T0 = 0.f, T1 = 0.f, N0 = 0.f, N1 = 0.f;
            for (int n4 = n0; n4 < n0 + 256; n4 += 4) {
                float4 ec4 = *(const float4*)(eyc + n4);
                float4 en4 = *(const float4*)(eyn + n4);
                const float* ecp = (const float*)&ec4;
                const float* enp = (const float*)&en4;
#pragma unroll
                for (int kk = 0; kk < 4; kk++) {
                    int n = n4 + kk;
                    float2 ex = exv[n * 32];
                    float2 o;
                    o.x = ecp[kk] * ex.x * invx;
                    o.y = ecp[kk] * ex.y * invy;
                    *(float2*)(orow + (size_t)n * PIX) = o;

                    float q0 = enp[kk] * ex.x, q1 = enp[kk] * ex.y;
                    T0 += q0; T1 += q1;
                    N0 = fmaxf(N0, q0); N1 = fmaxf(N1, q1);
                }
            }
            int buf = (k + 1) & 1;
            sP4[((buf * 2 + nh) * 4 + rw) * 32 + jp] =
                make_float4(T0, T1, N0, N1);
            __syncthreads();
            float4 a = sP4[((buf * 2 + 0) * 4 + rw) * 32 + jp];
            float4 q = sP4[((buf * 2 + 1) * 4 + rw) * 32 + jp];
            float bgx, bgy;
            finalize_sm(a.x + q.x, a.y + q.y,
                        fmaxf(a.z, q.z), fmaxf(a.w, q.w),
                        d, invx, invy, bgx, bgy);
            if (nh == 0)
                *(float2*)(bgrow + (4 * k + 4 + i0 + rw) * NC + jp * 2) =
                    make_float2(bgx, bgy);
        } else {
            for (int n4 = n0; n4 < n0 + 256; n4 += 4) {
                float4 ec4 = *(const float4*)(eyc + n4);
                const float* ecp = (const float*)&ec4;
#pragma unroll
                for (int kk = 0; kk < 4; kk++) {
                    int n = n4 + kk;
                    float2 ex = exv[n * 32];
                    float2 o;
                    o.x = ecp[kk] * ex.x * invx;
                    o.y = ecp[kk] * ex.y * invy;
                    *(float2*)(orow + (size_t)n * PIX) = o;
                }
            }
        }
    }
}

// ---------------------------------------------------------------------------
extern "C" void kernel_launch(void* const* d_in, const int* in_sizes, int n_in,
                              void* d_out, int out_size) {
    const float* points   = (const float*)d_in[0];
    const float* st_sizes = (const float*)d_in[1];
    const float* cood     = (const float*)d_in[2];
    float*       out      = (float*)d_out;

    cudaFuncSetAttribute(post_prob_kernel,
                         cudaFuncAttributeMaxDynamicSharedMemorySize,
                         SMEM_BYTES);

    post_prob_kernel<<<NB * 4, 256, SMEM_BYTES>>>(points, st_sizes, cood, out);
}